// round 7
// baseline (speedup 1.0000x reference)
#include <cuda_runtime.h>
#include <cuda_fp16.h>
#include <cstdint>

// GraphSAGE 2-layer, D=64, fp32 math — CSR gather (fp16 rows, MLP-16) + f32x2 combine.
//
//   layer: out = h @ W_self + mean_{in}(h) @ W_neigh + b
//   h1 = relu(layer1(x)); out = layer2(h1)
//
// R7: gather was latency-bound (MLP~4). Inner loop now issues 16 independent
// predicated row loads per stripe before consuming any -> MLP~16.
//
// Launch sequence (8 kernels, graph-capturable, no runtime API calls):
//   1 init(zero_cnt+x->fp16)  2 hist(+rank)  3 scan  4 fill
//   5 gather<x16>  6 combine(relu,->h1+h1fp16)  7 gather<h1_16>  8 combine(->out)

#define D 64
#define MAXN 50048
#define MAXE 850000
#define SCAN_THREADS 1024

__device__ float  g_mean[MAXN * D];   // neighbor MEAN rows (fp32)
__device__ float  g_h1[MAXN * D];     // layer-1 activations fp32 (self path)
__device__ __half g_x16[MAXN * D];    // fp16 copy of x     (gather path)
__device__ __half g_h116[MAXN * D];   // fp16 copy of h1    (gather path)
__device__ int    g_cnt[MAXN];        // in-degree
__device__ int    g_rowstart[MAXN];   // CSR offsets
__device__ int    g_rank[MAXE];       // per-edge rank within dst row
__device__ int    g_edge[MAXE];       // CSR column (src) indices

typedef unsigned long long u64;

__device__ __forceinline__ u64 pk2(float a, float b) {
    u64 r;
    asm("mov.b64 %0, {%1, %2};" : "=l"(r)
        : "r"(__float_as_uint(a)), "r"(__float_as_uint(b)));
    return r;
}
__device__ __forceinline__ void upk2(u64 v, float& a, float& b) {
    unsigned int x, y;
    asm("mov.b64 {%0, %1}, %2;" : "=r"(x), "=r"(y) : "l"(v));
    a = __uint_as_float(x);
    b = __uint_as_float(y);
}
__device__ __forceinline__ u64 fma2(u64 a, u64 b, u64 c) {
    u64 d;
    asm("fma.rn.f32x2 %0, %1, %2, %3;" : "=l"(d) : "l"(a), "l"(b), "l"(c));
    return d;
}

// ---------------------------------------------------------------------------
// init: zero degree counters AND convert x -> fp16 (independent elementwise).
// ---------------------------------------------------------------------------
__global__ void init_kernel(const float* __restrict__ x, int n) {
    int i = blockIdx.x * blockDim.x + threadIdx.x;
    if (i < n) g_cnt[i] = 0;
    int total4 = n * (D / 4);
    for (int j = i; j < total4; j += gridDim.x * blockDim.x) {
        float4 v = reinterpret_cast<const float4*>(x)[j];
        reinterpret_cast<__half2*>(g_x16)[j * 2 + 0] = __floats2half2_rn(v.x, v.y);
        reinterpret_cast<__half2*>(g_x16)[j * 2 + 1] = __floats2half2_rn(v.z, v.w);
    }
}

__global__ void hist_kernel(const int* __restrict__ dst, int E) {
    int e = blockIdx.x * blockDim.x + threadIdx.x;
    if (e < E) g_rank[e] = atomicAdd(&g_cnt[__ldg(dst + e)], 1);
}

__global__ void __launch_bounds__(SCAN_THREADS)
scan_kernel(int n) {
    __shared__ int s[SCAN_THREADS];
    int t = threadIdx.x;
    int items = (n + SCAN_THREADS - 1) / SCAN_THREADS;
    int lo = t * items;
    int hi = min(n, lo + items);

    int sum = 0;
    for (int i = lo; i < hi; i++) sum += g_cnt[i];
    s[t] = sum;
    __syncthreads();
    for (int off = 1; off < SCAN_THREADS; off <<= 1) {
        int v = (t >= off) ? s[t - off] : 0;
        __syncthreads();
        s[t] += v;
        __syncthreads();
    }
    int base = (t == 0) ? 0 : s[t - 1];
    for (int i = lo; i < hi; i++) {
        g_rowstart[i] = base;
        base += g_cnt[i];
    }
}

__global__ void fill_kernel(const int* __restrict__ src,
                            const int* __restrict__ dst, int E) {
    int e = blockIdx.x * blockDim.x + threadIdx.x;
    if (e < E) {
        int d = __ldg(dst + e);
        g_edge[g_rowstart[d] + g_rank[e]] = __ldg(src + e);
    }
}

// ---------------------------------------------------------------------------
// Gather v4: warp per node, fp16 rows, MLP-16.
// Stripe of 16 neighbors: shfl all 16 indices, issue all 16 predicated
// half2 LDGs (independent), THEN unpack+accumulate in fp32.
// ---------------------------------------------------------------------------
template <bool FROM_H1>
__global__ void __launch_bounds__(256)
gather_kernel(int n) {
    const __half2* __restrict__ base = reinterpret_cast<const __half2*>(
        FROM_H1 ? (const __half*)g_h116 : (const __half*)g_x16);

    int warp = (blockIdx.x * blockDim.x + threadIdx.x) >> 5;
    if (warp >= n) return;
    int lane = threadIdx.x & 31;

    int start = g_rowstart[warp];
    int deg   = g_cnt[warp];

    float ax = 0.f, ay = 0.f;

    for (int j0 = 0; j0 < deg; j0 += 16) {
        int nj = min(16, deg - j0);               // 1..16, warp-uniform
        int myidx = (lane < nj) ? __ldg(g_edge + start + j0 + lane) : 0;

        __half2 v[16];
#pragma unroll
        for (int j = 0; j < 16; j++) {
            int s = __shfl_sync(0xffffffffu, myidx, j);
            if (j < nj)
                v[j] = __ldg(base + (size_t)s * 32 + lane);
        }
#pragma unroll
        for (int j = 0; j < 16; j++) {
            if (j < nj) {
                float2 f = __half22float2(v[j]);
                ax += f.x;
                ay += f.y;
            }
        }
    }

    float inv = 1.0f / fmaxf((float)deg, 1.0f);
    float2 m; m.x = ax * inv; m.y = ay * inv;
    reinterpret_cast<float2*>(g_mean)[(size_t)warp * 32 + lane] = m;
}

// ---------------------------------------------------------------------------
// Combine: out = h@W_self + mean@W_neigh + b [+relu]; f32x2 register tile.
// TO_H1 additionally stores fp16 copy (g_h116) for the next gather.
// ---------------------------------------------------------------------------
template <bool RELU, bool FROM_H1, bool TO_H1>
__global__ void __launch_bounds__(256, 2)
combine_kernel(const float* __restrict__ h_in,
               const float* __restrict__ Wself,
               const float* __restrict__ Wneigh,
               const float* __restrict__ bias,
               float* __restrict__ out_in, int n) {
    const float* __restrict__ h = FROM_H1 ? (const float*)g_h1 : h_in;
    float* __restrict__ out     = TO_H1 ? (float*)g_h1 : out_in;

    __shared__ float sWs[D * D];
    __shared__ float sWn[D * D];

    int tid = threadIdx.x;
    for (int i = tid; i < D * D / 4; i += 256) {
        reinterpret_cast<float4*>(sWs)[i] =
            reinterpret_cast<const float4*>(Wself)[i];
        reinterpret_cast<float4*>(sWn)[i] =
            reinterpret_cast<const float4*>(Wneigh)[i];
    }
    __syncthreads();

    int cg = tid & 15;
    int c0 = cg * 4;
    int ng = tid >> 4;
    int nbase = blockIdx.x * 64 + ng * 4;

    bool valid[4];
#pragma unroll
    for (int i = 0; i < 4; i++) valid[i] = (nbase + i) < n;

    u64 b01 = pk2(__ldg(bias + c0 + 0), __ldg(bias + c0 + 1));
    u64 b23 = pk2(__ldg(bias + c0 + 2), __ldg(bias + c0 + 3));

    u64 acc[4][2];
#pragma unroll
    for (int i = 0; i < 4; i++) { acc[i][0] = b01; acc[i][1] = b23; }

#pragma unroll 4
    for (int k0 = 0; k0 < D; k0 += 4) {
        float4 xv[4], mv[4];
#pragma unroll
        for (int i = 0; i < 4; i++) {
            if (valid[i]) {
                xv[i] = *reinterpret_cast<const float4*>(
                    h + (size_t)(nbase + i) * D + k0);
                mv[i] = *reinterpret_cast<const float4*>(
                    g_mean + (size_t)(nbase + i) * D + k0);
            } else {
                xv[i] = make_float4(0.f, 0.f, 0.f, 0.f);
                mv[i] = make_float4(0.f, 0.f, 0.f, 0.f);
            }
        }

#pragma unroll
        for (int j = 0; j < 4; j++) {
            int k = k0 + j;
            float4 ws = *reinterpret_cast<const float4*>(sWs + k * D + c0);
            float4 wn = *reinterpret_cast<const float4*>(sWn + k * D + c0);
            u64 ws01 = pk2(ws.x, ws.y), ws23 = pk2(ws.z, ws.w);
            u64 wn01 = pk2(wn.x, wn.y), wn23 = pk2(wn.z, wn.w);
#pragma unroll
            for (int i = 0; i < 4; i++) {
                float xk = (j == 0) ? xv[i].x : (j == 1) ? xv[i].y
                          : (j == 2) ? xv[i].z : xv[i].w;
                float mk = (j == 0) ? mv[i].x : (j == 1) ? mv[i].y
                          : (j == 2) ? mv[i].z : mv[i].w;
                u64 xx = pk2(xk, xk);
                u64 mm = pk2(mk, mk);
                acc[i][0] = fma2(xx, ws01, acc[i][0]);
                acc[i][0] = fma2(mm, wn01, acc[i][0]);
                acc[i][1] = fma2(xx, ws23, acc[i][1]);
                acc[i][1] = fma2(mm, wn23, acc[i][1]);
            }
        }
    }

#pragma unroll
    for (int i = 0; i < 4; i++) {
        if (!valid[i]) continue;
        float a0, a1, a2, a3;
        upk2(acc[i][0], a0, a1);
        upk2(acc[i][1], a2, a3);
        if (RELU) {
            a0 = fmaxf(a0, 0.f); a1 = fmaxf(a1, 0.f);
            a2 = fmaxf(a2, 0.f); a3 = fmaxf(a3, 0.f);
        }
        *reinterpret_cast<float4*>(out + (size_t)(nbase + i) * D + c0) =
            make_float4(a0, a1, a2, a3);
        if (TO_H1) {
            __half2* p = reinterpret_cast<__half2*>(
                g_h116 + (size_t)(nbase + i) * D + c0);
            p[0] = __floats2half2_rn(a0, a1);
            p[1] = __floats2half2_rn(a2, a3);
        }
    }
}

// ---------------------------------------------------------------------------
extern "C" void kernel_launch(void* const* d_in, const int* in_sizes, int n_in,
                              void* d_out, int out_size) {
    const float* x        = (const float*)d_in[0];
    const int*   src      = (const int*)d_in[1];
    const int*   dst      = (const int*)d_in[2];
    const float* W1_self  = (const float*)d_in[3];
    const float* W1_neigh = (const float*)d_in[4];
    const float* b1       = (const float*)d_in[5];
    const float* W2_self  = (const float*)d_in[6];
    const float* W2_neigh = (const float*)d_in[7];
    const float* b2       = (const float*)d_in[8];
    float* out = (float*)d_out;

    int n = in_sizes[0] / D;
    int E = in_sizes[1];

    int eb = (E + 255) / 256;
    int nb = (n + 255) / 256;
    int gb = (n * 32 + 255) / 256;     // warp per node
    int cb = (n + 63) / 64;

    // ---- CSR build + fp16 convert ----
    init_kernel<<<nb, 256>>>(x, n);
    hist_kernel<<<eb, 256>>>(dst, E);
    scan_kernel<<<1, SCAN_THREADS>>>(n);
    fill_kernel<<<eb, 256>>>(src, dst, E);

    // ---- layer 1 ----  (x -> g_h1 fp32 + g_h116 fp16, relu)
    gather_kernel<false><<<gb, 256>>>(n);
    combine_kernel<true, false, true>
        <<<cb, 256>>>(x, W1_self, W1_neigh, b1, nullptr, n);

    // ---- layer 2 ----  (g_h1 -> out)
    gather_kernel<true><<<gb, 256>>>(n);
    combine_kernel<false, true, false>
        <<<cb, 256>>>(nullptr, W2_self, W2_neigh, b2, out, n);
}

// round 8
// speedup vs baseline: 1.2364x; 1.2364x over previous
#include <cuda_runtime.h>
#include <cstdint>

// GraphSAGE 2-layer, D=64, fp32 — single persistent kernel.
//   layer: out = h @ W_self + mean_{in}(h) @ W_neigh + b
//   h1 = relu(layer1(x)); out = layer2(h1)
//
// One launch <<<148, 768>>> (1 block per SM, single wave => co-resident),
// 5 phases separated by 4 sense-reversing grid barriers:
//   zero(sum1,sum2,deg) | scatter1(RED) | combine1(relu,->h1) |
//   scatter2(RED)       | combine2(->out)
// Ping-pong sum buffers avoid any rezero between layers.

#define D 64
#define MAXN 50048
#define NBLK 148
#define NTHR 768
#define NGROUP (NTHR / 256)

__device__ float g_sum1[MAXN * D];
__device__ float g_sum2[MAXN * D];
__device__ float g_deg[MAXN];
__device__ float g_h1[MAXN * D];
__device__ unsigned g_bar_count;            // zero-init; returns to 0
__device__ volatile unsigned g_bar_sense;   // zero-init; 4 flips -> back to 0

typedef unsigned long long u64;

__device__ __forceinline__ u64 pk2(float a, float b) {
    u64 r;
    asm("mov.b64 %0, {%1, %2};" : "=l"(r)
        : "r"(__float_as_uint(a)), "r"(__float_as_uint(b)));
    return r;
}
__device__ __forceinline__ void upk2(u64 v, float& a, float& b) {
    unsigned int x, y;
    asm("mov.b64 {%0, %1}, %2;" : "=r"(x), "=r"(y) : "l"(v));
    a = __uint_as_float(x);
    b = __uint_as_float(y);
}
__device__ __forceinline__ u64 fma2(u64 a, u64 b, u64 c) {
    u64 d;
    asm("fma.rn.f32x2 %0, %1, %2, %3;" : "=l"(d) : "l"(a), "l"(b), "l"(c));
    return d;
}

// ---------------------------------------------------------------------------
// Sense-reversing grid barrier. gpu-scope fences on both sides (release on
// arrive, acquire + L1D invalidate after wait) so RED/STG results from other
// SMs are visible and stale L1 lines are dropped.
// ---------------------------------------------------------------------------
__device__ __forceinline__ void grid_barrier(unsigned& sense) {
    __syncthreads();
    if (threadIdx.x == 0) {
        sense ^= 1u;
        __threadfence();                                   // release
        unsigned arrived = atomicAdd(&g_bar_count, 1u) + 1u;
        if (arrived == NBLK) {
            g_bar_count = 0;
            __threadfence();                               // reset before flip
            g_bar_sense = sense;
        } else {
            while (g_bar_sense != sense) __nanosleep(32);
        }
        __threadfence();                                   // acquire + CCTL.IVALL
    }
    __syncthreads();
}

// ---------------------------------------------------------------------------
// Scatter phase: item = (edge, 16B chunk); 16 items per edge.
// 8-deep batching: 8 index loads, then 8 independent float4 loads, then 8 REDs.
// ---------------------------------------------------------------------------
__device__ void scatter_phase(const float* __restrict__ h,
                              const int* __restrict__ src,
                              const int* __restrict__ dst,
                              int E, float* __restrict__ sum, bool count_deg) {
    const long long total  = (long long)E * 16;
    const long long stride = (long long)NBLK * NTHR;
    long long idx = (long long)blockIdx.x * NTHR + threadIdx.x;

    while (idx + 7 * stride < total) {
        int sA[8], dA[8], cA[8];
#pragma unroll
        for (int u = 0; u < 8; u++) {
            long long it = idx + (long long)u * stride;
            int e = (int)(it >> 4);
            cA[u] = ((int)it & 15) * 4;
            sA[u] = __ldg(src + e);
            dA[u] = __ldg(dst + e);
        }
        float4 vA[8];
#pragma unroll
        for (int u = 0; u < 8; u++)
            vA[u] = *reinterpret_cast<const float4*>(
                h + (size_t)sA[u] * D + cA[u]);
#pragma unroll
        for (int u = 0; u < 8; u++) {
            float* p = sum + (size_t)dA[u] * D + cA[u];
            asm volatile("red.global.add.v4.f32 [%0], {%1,%2,%3,%4};"
                         :: "l"(p), "f"(vA[u].x), "f"(vA[u].y),
                            "f"(vA[u].z), "f"(vA[u].w) : "memory");
            if (count_deg && cA[u] == 0)
                asm volatile("red.global.add.f32 [%0], %1;"
                             :: "l"(g_deg + dA[u]), "f"(1.0f) : "memory");
        }
        idx += 8 * stride;
    }
    for (; idx < total; idx += stride) {
        int e = (int)(idx >> 4);
        int c = ((int)idx & 15) * 4;
        int s = __ldg(src + e);
        int d = __ldg(dst + e);
        float4 v = *reinterpret_cast<const float4*>(h + (size_t)s * D + c);
        float* p = sum + (size_t)d * D + c;
        asm volatile("red.global.add.v4.f32 [%0], {%1,%2,%3,%4};"
                     :: "l"(p), "f"(v.x), "f"(v.y), "f"(v.z), "f"(v.w)
                     : "memory");
        if (count_deg && c == 0)
            asm volatile("red.global.add.f32 [%0], %1;"
                         :: "l"(g_deg + d), "f"(1.0f) : "memory");
    }
}

// ---------------------------------------------------------------------------
// Combine phase: out = h@W_self + (sum/deg)@W_neigh + b [+relu].
// NTHR = 3 groups of 256; group handles 64-node tiles strided NBLK*3.
// Per 256-group: 16 col-groups x 16 node-groups of 4 nodes; f32x2 FMAs.
// Weights staged once per phase.
// ---------------------------------------------------------------------------
template <bool RELU>
__device__ void combine_phase(const float* __restrict__ h,
                              const float* __restrict__ sum,
                              const float* __restrict__ Wself,
                              const float* __restrict__ Wneigh,
                              const float* __restrict__ bias,
                              float* __restrict__ out, int n,
                              float* sWs, float* sWn) {
    int tid = threadIdx.x;
    for (int i = tid; i < D * D / 4; i += NTHR) {
        reinterpret_cast<float4*>(sWs)[i] =
            reinterpret_cast<const float4*>(Wself)[i];
        reinterpret_cast<float4*>(sWn)[i] =
            reinterpret_cast<const float4*>(Wneigh)[i];
    }
    __syncthreads();

    int sub = tid & 255;
    int grp = tid >> 8;
    int cg = sub & 15;
    int c0 = cg * 4;
    int ng = sub >> 4;
    int ntiles = (n + 63) / 64;

    u64 b01 = pk2(__ldg(bias + c0 + 0), __ldg(bias + c0 + 1));
    u64 b23 = pk2(__ldg(bias + c0 + 2), __ldg(bias + c0 + 3));

    for (int tile = blockIdx.x * NGROUP + grp; tile < ntiles;
         tile += NBLK * NGROUP) {
        int nbase = tile * 64 + ng * 4;

        bool valid[4];
        float invd[4];
#pragma unroll
        for (int i = 0; i < 4; i++) {
            valid[i] = (nbase + i) < n;
            invd[i] = valid[i] ? (1.0f / fmaxf(g_deg[nbase + i], 1.0f)) : 0.f;
        }

        u64 acc[4][2];
#pragma unroll
        for (int i = 0; i < 4; i++) { acc[i][0] = b01; acc[i][1] = b23; }

#pragma unroll 4
        for (int k0 = 0; k0 < D; k0 += 4) {
            float4 xv[4], mv[4];
#pragma unroll
            for (int i = 0; i < 4; i++) {
                if (valid[i]) {
                    xv[i] = *reinterpret_cast<const float4*>(
                        h + (size_t)(nbase + i) * D + k0);
                    float4 sv = *reinterpret_cast<const float4*>(
                        sum + (size_t)(nbase + i) * D + k0);
                    mv[i] = make_float4(sv.x * invd[i], sv.y * invd[i],
                                        sv.z * invd[i], sv.w * invd[i]);
                } else {
                    xv[i] = make_float4(0.f, 0.f, 0.f, 0.f);
                    mv[i] = make_float4(0.f, 0.f, 0.f, 0.f);
                }
            }
#pragma unroll
            for (int j = 0; j < 4; j++) {
                int k = k0 + j;
                float4 ws = *reinterpret_cast<const float4*>(sWs + k * D + c0);
                float4 wn = *reinterpret_cast<const float4*>(sWn + k * D + c0);
                u64 ws01 = pk2(ws.x, ws.y), ws23 = pk2(ws.z, ws.w);
                u64 wn01 = pk2(wn.x, wn.y), wn23 = pk2(wn.z, wn.w);
#pragma unroll
                for (int i = 0; i < 4; i++) {
                    float xk = (j == 0) ? xv[i].x : (j == 1) ? xv[i].y
                              : (j == 2) ? xv[i].z : xv[i].w;
                    float mk = (j == 0) ? mv[i].x : (j == 1) ? mv[i].y
                              : (j == 2) ? mv[i].z : mv[i].w;
                    u64 xx = pk2(xk, xk);
                    u64 mm = pk2(mk, mk);
                    acc[i][0] = fma2(xx, ws01, acc[i][0]);
                    acc[i][0] = fma2(mm, wn01, acc[i][0]);
                    acc[i][1] = fma2(xx, ws23, acc[i][1]);
                    acc[i][1] = fma2(mm, wn23, acc[i][1]);
                }
            }
        }

#pragma unroll
        for (int i = 0; i < 4; i++) {
            if (!valid[i]) continue;
            float a0, a1, a2, a3;
            upk2(acc[i][0], a0, a1);
            upk2(acc[i][1], a2, a3);
            if (RELU) {
                a0 = fmaxf(a0, 0.f); a1 = fmaxf(a1, 0.f);
                a2 = fmaxf(a2, 0.f); a3 = fmaxf(a3, 0.f);
            }
            *reinterpret_cast<float4*>(out + (size_t)(nbase + i) * D + c0) =
                make_float4(a0, a1, a2, a3);
        }
    }
}

// ---------------------------------------------------------------------------
__global__ void __launch_bounds__(NTHR)
sage_kernel(const float* __restrict__ x,
            const int* __restrict__ src,
            const int* __restrict__ dst,
            const float* __restrict__ W1s, const float* __restrict__ W1n,
            const float* __restrict__ b1,
            const float* __restrict__ W2s, const float* __restrict__ W2n,
            const float* __restrict__ b2,
            float* __restrict__ out, int n, int E) {
    __shared__ float sWs[D * D];
    __shared__ float sWn[D * D];

    unsigned sense = 0;
    int tid_g = blockIdx.x * NTHR + threadIdx.x;
    const int gstride = NBLK * NTHR;

    // ---- phase 0: zero both sum buffers + degrees ----
    {
        float4 z = make_float4(0.f, 0.f, 0.f, 0.f);
        int total4 = n * (D / 4);
        for (int i = tid_g; i < total4; i += gstride) {
            reinterpret_cast<float4*>(g_sum1)[i] = z;
            reinterpret_cast<float4*>(g_sum2)[i] = z;
        }
        for (int i = tid_g; i < n; i += gstride) g_deg[i] = 0.f;
    }
    grid_barrier(sense);

    // ---- phase 1: scatter layer 1 ----
    scatter_phase(x, src, dst, E, g_sum1, true);
    grid_barrier(sense);

    // ---- phase 2: combine layer 1 (relu) -> g_h1 ----
    combine_phase<true>(x, g_sum1, W1s, W1n, b1, g_h1, n, sWs, sWn);
    grid_barrier(sense);

    // ---- phase 3: scatter layer 2 ----
    scatter_phase(g_h1, src, dst, E, g_sum2, false);
    grid_barrier(sense);

    // ---- phase 4: combine layer 2 -> out ----
    combine_phase<false>(g_h1, g_sum2, W2s, W2n, b2, out, n, sWs, sWn);
}

// ---------------------------------------------------------------------------
extern "C" void kernel_launch(void* const* d_in, const int* in_sizes, int n_in,
                              void* d_out, int out_size) {
    const float* x        = (const float*)d_in[0];
    const int*   src      = (const int*)d_in[1];
    const int*   dst      = (const int*)d_in[2];
    const float* W1_self  = (const float*)d_in[3];
    const float* W1_neigh = (const float*)d_in[4];
    const float* b1       = (const float*)d_in[5];
    const float* W2_self  = (const float*)d_in[6];
    const float* W2_neigh = (const float*)d_in[7];
    const float* b2       = (const float*)d_in[8];
    float* out = (float*)d_out;

    int n = in_sizes[0] / D;
    int E = in_sizes[1];

    sage_kernel<<<NBLK, NTHR>>>(x, src, dst,
                                W1_self, W1_neigh, b1,
                                W2_self, W2_neigh, b2,
                                out, n, E);
}

// round 9
// speedup vs baseline: 1.3488x; 1.0909x over previous
#include <cuda_runtime.h>
#include <cstdint>

// GraphSAGE 2-layer, D=64, fp32 — single persistent kernel, padded-CSR gather.
//   layer: out = h @ W_self + mean_{in}(h) @ W_neigh + b
//   h1 = relu(layer1(x)); out = layer2(h1)
//
// One launch <<<148, 768>>>, 9 phases / 8 grid barriers:
//   0 copy x->g_x (+zero pad row), zero g_h1 pad row, zero cnt
//   1 hist (rank = atomicAdd(cnt[dst]))
//   2a block-local padded-count scan          2b global base + rowstart + pad edges
//   3 fill CSR (atomic-free: rowstart+rank)
//   4 gather1 (g_x -> g_mean)   5 combine1 (relu -> g_h1)
//   6 gather2 (g_h1 -> g_mean)  7 combine2 (-> out)
//
// Gather: warp per node; degree padded to 8; sentinel edges point at row `n`
// (zeroed) so the inner loop has NO predication and NO tail. 8 broadcast index
// LDGs then 8 independent row LDGs per stripe (MLP ~8-16). No float atomics.

#define D 64
#define MAXN 50048
#define MAXEP 1200000          // padded edge capacity: 800k + 50k*7 < 1.2M
#define NBLK 148
#define NTHR 768
#define NGROUP (NTHR / 256)

__device__ float g_x[MAXN * D];       // fp32 copy of x, row n zeroed
__device__ float g_h1[MAXN * D];      // layer-1 activations, row n zeroed
__device__ float g_mean[MAXN * D];    // neighbor means
__device__ int   g_cnt[MAXN];         // true in-degree
__device__ int   g_rowstart[MAXN];    // padded CSR offsets
__device__ int   g_rank[MAXEP];       // per-edge rank within dst row
__device__ int   g_edge[MAXEP];       // CSR src indices (+ sentinel padding)
__device__ int   g_part[NBLK];        // scan partials
__device__ unsigned g_bar_count;           // returns to 0
__device__ volatile unsigned g_bar_sense;  // 8 flips -> returns to 0

typedef unsigned long long u64;

__device__ __forceinline__ u64 pk2(float a, float b) {
    u64 r;
    asm("mov.b64 %0, {%1, %2};" : "=l"(r)
        : "r"(__float_as_uint(a)), "r"(__float_as_uint(b)));
    return r;
}
__device__ __forceinline__ void upk2(u64 v, float& a, float& b) {
    unsigned int x, y;
    asm("mov.b64 {%0, %1}, %2;" : "=r"(x), "=r"(y) : "l"(v));
    a = __uint_as_float(x);
    b = __uint_as_float(y);
}
__device__ __forceinline__ u64 fma2(u64 a, u64 b, u64 c) {
    u64 d;
    asm("fma.rn.f32x2 %0, %1, %2, %3;" : "=l"(d) : "l"(a), "l"(b), "l"(c));
    return d;
}

// Sense-reversing grid barrier (identical to the validated R8 version).
__device__ __forceinline__ void grid_barrier(unsigned& sense) {
    __syncthreads();
    if (threadIdx.x == 0) {
        sense ^= 1u;
        __threadfence();
        unsigned arrived = atomicAdd(&g_bar_count, 1u) + 1u;
        if (arrived == NBLK) {
            g_bar_count = 0;
            __threadfence();
            g_bar_sense = sense;
        } else {
            while (g_bar_sense != sense) __nanosleep(32);
        }
        __threadfence();
    }
    __syncthreads();
}

// ---------------------------------------------------------------------------
// Gather: warp per node, padded neighbor list, branch-free inner loop.
// Lane owns float2 at column lane*2. Writes the MEAN row.
// ---------------------------------------------------------------------------
__device__ void gather_phase(const float* __restrict__ feat, int n) {
    const float2* __restrict__ base = reinterpret_cast<const float2*>(feat);
    int nwarps = NBLK * (NTHR / 32);
    int gw = blockIdx.x * (NTHR / 32) + (threadIdx.x >> 5);
    int lane = threadIdx.x & 31;

    for (int node = gw; node < n; node += nwarps) {
        int start = g_rowstart[node];
        int cnt   = g_cnt[node];
        int degp  = (cnt + 7) & ~7;

        float ax = 0.f, ay = 0.f;
        const int* ep = g_edge + start;
        for (int j = 0; j < degp; j += 8) {
            int i0 = __ldg(ep + j + 0);
            int i1 = __ldg(ep + j + 1);
            int i2 = __ldg(ep + j + 2);
            int i3 = __ldg(ep + j + 3);
            int i4 = __ldg(ep + j + 4);
            int i5 = __ldg(ep + j + 5);
            int i6 = __ldg(ep + j + 6);
            int i7 = __ldg(ep + j + 7);
            float2 v0 = __ldg(base + (size_t)i0 * 32 + lane);
            float2 v1 = __ldg(base + (size_t)i1 * 32 + lane);
            float2 v2 = __ldg(base + (size_t)i2 * 32 + lane);
            float2 v3 = __ldg(base + (size_t)i3 * 32 + lane);
            float2 v4 = __ldg(base + (size_t)i4 * 32 + lane);
            float2 v5 = __ldg(base + (size_t)i5 * 32 + lane);
            float2 v6 = __ldg(base + (size_t)i6 * 32 + lane);
            float2 v7 = __ldg(base + (size_t)i7 * 32 + lane);
            ax += v0.x + v1.x + v2.x + v3.x + v4.x + v5.x + v6.x + v7.x;
            ay += v0.y + v1.y + v2.y + v3.y + v4.y + v5.y + v6.y + v7.y;
        }
        float inv = 1.0f / fmaxf((float)cnt, 1.0f);
        float2 m; m.x = ax * inv; m.y = ay * inv;
        reinterpret_cast<float2*>(g_mean)[(size_t)node * 32 + lane] = m;
    }
}

// ---------------------------------------------------------------------------
// Combine: out = h@W_self + mean@W_neigh + b [+relu]; f32x2 register tile.
// ---------------------------------------------------------------------------
template <bool RELU>
__device__ void combine_phase(const float* __restrict__ h,
                              const float* __restrict__ Wself,
                              const float* __restrict__ Wneigh,
                              const float* __restrict__ bias,
                              float* __restrict__ out, int n,
                              float* sWs, float* sWn) {
    int tid = threadIdx.x;
    for (int i = tid; i < D * D / 4; i += NTHR) {
        reinterpret_cast<float4*>(sWs)[i] =
            reinterpret_cast<const float4*>(Wself)[i];
        reinterpret_cast<float4*>(sWn)[i] =
            reinterpret_cast<const float4*>(Wneigh)[i];
    }
    __syncthreads();

    int sub = tid & 255;
    int grp = tid >> 8;
    int cg = sub & 15;
    int c0 = cg * 4;
    int ng = sub >> 4;
    int ntiles = (n + 63) / 64;

    u64 b01 = pk2(__ldg(bias + c0 + 0), __ldg(bias + c0 + 1));
    u64 b23 = pk2(__ldg(bias + c0 + 2), __ldg(bias + c0 + 3));

    for (int tile = blockIdx.x * NGROUP + grp; tile < ntiles;
         tile += NBLK * NGROUP) {
        int nbase = tile * 64 + ng * 4;

        bool valid[4];
#pragma unroll
        for (int i = 0; i < 4; i++) valid[i] = (nbase + i) < n;

        u64 acc[4][2];
#pragma unroll
        for (int i = 0; i < 4; i++) { acc[i][0] = b01; acc[i][1] = b23; }

#pragma unroll 4
        for (int k0 = 0; k0 < D; k0 += 4) {
            float4 xv[4], mv[4];
#pragma unroll
            for (int i = 0; i < 4; i++) {
                if (valid[i]) {
                    xv[i] = *reinterpret_cast<const float4*>(
                        h + (size_t)(nbase + i) * D + k0);
                    mv[i] = *reinterpret_cast<const float4*>(
                        g_mean + (size_t)(nbase + i) * D + k0);
                } else {
                    xv[i] = make_float4(0.f, 0.f, 0.f, 0.f);
                    mv[i] = make_float4(0.f, 0.f, 0.f, 0.f);
                }
            }
#pragma unroll
            for (int j = 0; j < 4; j++) {
                int k = k0 + j;
                float4 ws = *reinterpret_cast<const float4*>(sWs + k * D + c0);
                float4 wn = *reinterpret_cast<const float4*>(sWn + k * D + c0);
                u64 ws01 = pk2(ws.x, ws.y), ws23 = pk2(ws.z, ws.w);
                u64 wn01 = pk2(wn.x, wn.y), wn23 = pk2(wn.z, wn.w);
#pragma unroll
                for (int i = 0; i < 4; i++) {
                    float xk = (j == 0) ? xv[i].x : (j == 1) ? xv[i].y
                              : (j == 2) ? xv[i].z : xv[i].w;
                    float mk = (j == 0) ? mv[i].x : (j == 1) ? mv[i].y
                              : (j == 2) ? mv[i].z : mv[i].w;
                    u64 xx = pk2(xk, xk);
                    u64 mm = pk2(mk, mk);
                    acc[i][0] = fma2(xx, ws01, acc[i][0]);
                    acc[i][0] = fma2(mm, wn01, acc[i][0]);
                    acc[i][1] = fma2(xx, ws23, acc[i][1]);
                    acc[i][1] = fma2(mm, wn23, acc[i][1]);
                }
            }
        }

#pragma unroll
        for (int i = 0; i < 4; i++) {
            if (!valid[i]) continue;
            float a0, a1, a2, a3;
            upk2(acc[i][0], a0, a1);
            upk2(acc[i][1], a2, a3);
            if (RELU) {
                a0 = fmaxf(a0, 0.f); a1 = fmaxf(a1, 0.f);
                a2 = fmaxf(a2, 0.f); a3 = fmaxf(a3, 0.f);
            }
            *reinterpret_cast<float4*>(out + (size_t)(nbase + i) * D + c0) =
                make_float4(a0, a1, a2, a3);
        }
    }
}

// ---------------------------------------------------------------------------
__global__ void __launch_bounds__(NTHR)
sage_kernel(const float* __restrict__ x,
            const int* __restrict__ src,
            const int* __restrict__ dst,
            const float* __restrict__ W1s, const float* __restrict__ W1n,
            const float* __restrict__ b1,
            const float* __restrict__ W2s, const float* __restrict__ W2n,
            const float* __restrict__ b2,
            float* __restrict__ out, int n, int E) {
    __shared__ float sWs[D * D];     // 16 KB (also reused as int scan buffer)
    __shared__ float sWn[D * D];     // 16 KB

    unsigned sense = 0;
    const int tid_g = blockIdx.x * NTHR + threadIdx.x;
    const int gstride = NBLK * NTHR;
    const int t = threadIdx.x;

    // ---- phase 0: copy x -> g_x, zero pad rows, zero counters ----
    {
        int total4 = n * (D / 4);
        for (int i = tid_g; i < total4; i += gstride)
            reinterpret_cast<float4*>(g_x)[i] =
                reinterpret_cast<const float4*>(x)[i];
        for (int i = tid_g; i < n; i += gstride) g_cnt[i] = 0;
        if (blockIdx.x == 0 && t < D / 4) {
            float4 z = make_float4(0.f, 0.f, 0.f, 0.f);
            reinterpret_cast<float4*>(g_x + (size_t)n * D)[t] = z;
            reinterpret_cast<float4*>(g_h1 + (size_t)n * D)[t] = z;
        }
    }
    grid_barrier(sense);

    // ---- phase 1: histogram + rank capture ----
    for (int e = tid_g; e < E; e += gstride)
        g_rank[e] = atomicAdd(&g_cnt[__ldg(dst + e)], 1);
    grid_barrier(sense);

    // ---- phase 2a: block-local exclusive scan of padded counts ----
    int* s = reinterpret_cast<int*>(sWs);
    const int chunk = (n + NBLK - 1) / NBLK;       // <= NTHR required
    const int node = blockIdx.x * chunk + t;
    int padded = 0;
    if (t < chunk && node < n) padded = (g_cnt[node] + 7) & ~7;
    s[t] = padded;
    __syncthreads();
    for (int off = 1; off < NTHR; off <<= 1) {
        int v = (t >= off) ? s[t - off] : 0;
        __syncthreads();
        s[t] += v;
        __syncthreads();
    }
    int excl = s[t] - padded;                      // exclusive within block
    if (t == NTHR - 1) g_part[blockIdx.x] = s[NTHR - 1];
    grid_barrier(sense);

    // ---- phase 2b: global base, write rowstart + sentinel padding edges ----
    {
        int* sp = reinterpret_cast<int*>(sWn);
        if (t < NBLK) sp[t] = g_part[t];
        __syncthreads();
        int base = 0;
        for (int b = 0; b < blockIdx.x; b++) base += sp[b];
        if (t < chunk && node < n) {
            int rs = base + excl;
            g_rowstart[node] = rs;
            int cnt = g_cnt[node];
            int degp = (cnt + 7) & ~7;
            for (int j = cnt; j < degp; j++) g_edge[rs + j] = n;  // zero row
        }
    }
    grid_barrier(sense);

    // ---- phase 3: fill CSR (atomic-free) ----
    for (int e = tid_g; e < E; e += gstride) {
        int d = __ldg(dst + e);
        g_edge[g_rowstart[d] + g_rank[e]] = __ldg(src + e);
    }
    grid_barrier(sense);

    // ---- phase 4: gather layer 1 ----
    gather_phase(g_x, n);
    grid_barrier(sense);

    // ---- phase 5: combine layer 1 (relu) -> g_h1 ----
    combine_phase<true>(g_x, W1s, W1n, b1, g_h1, n, sWs, sWn);
    grid_barrier(sense);

    // ---- phase 6: gather layer 2 ----
    gather_phase(g_h1, n);
    grid_barrier(sense);

    // ---- phase 7: combine layer 2 -> out ----
    combine_phase<false>(g_h1, W2s, W2n, b2, out, n, sWs, sWn);
}

// ---------------------------------------------------------------------------
extern "C" void kernel_launch(void* const* d_in, const int* in_sizes, int n_in,
                              void* d_out, int out_size) {
    const float* x        = (const float*)d_in[0];
    const int*   src      = (const int*)d_in[1];
    const int*   dst      = (const int*)d_in[2];
    const float* W1_self  = (const float*)d_in[3];
    const float* W1_neigh = (const float*)d_in[4];
    const float* b1       = (const float*)d_in[5];
    const float* W2_self  = (const float*)d_in[6];
    const float* W2_neigh = (const float*)d_in[7];
    const float* b2       = (const float*)d_in[8];
    float* out = (float*)d_out;

    int n = in_sizes[0] / D;
    int E = in_sizes[1];

    sage_kernel<<<NBLK, NTHR>>>(x, src, dst,
                                W1_self, W1_neigh, b1,
                                W2_self, W2_neigh, b2,
                                out, n, E);
}

// round 10
// speedup vs baseline: 1.3687x; 1.0148x over previous
#include <cuda_runtime.h>
#include <cuda_fp16.h>
#include <cstdint>

// GraphSAGE 2-layer, D=64 — persistent kernel, padded-CSR gather over fp16 rows.
//   layer: out = h @ W_self + mean_{in}(h) @ W_neigh + b
//   h1 = relu(layer1(x)); out = layer2(h1)
//
// R10: gather was L1-wavefront-bound (fp32 row = 2 lines). fp16 rows = 1 line
// per neighbor row load. fp32 accumulation and fp32 GEMM path unchanged.
//
// One launch <<<148, 768>>>, phases / grid barriers as in R9:
//   0 x->g_x16 (+zero pad rows), zero cnt | 1 hist(+rank) | 2a/2b scan+pad
//   3 fill | 4 gather1 | 5 combine1(relu -> g_h1 + g_h116) | 6 gather2 | 7 combine2

#define D 64
#define MAXN 50048
#define MAXEP 1200000
#define NBLK 148
#define NTHR 768
#define NGROUP (NTHR / 256)

__device__ __half g_x16[MAXN * D];    // fp16 x rows, row n zeroed (sentinel)
__device__ __half g_h116[MAXN * D];   // fp16 h1 rows, row n zeroed
__device__ float  g_h1[MAXN * D];     // fp32 h1 (self path / GEMM)
__device__ float  g_mean[MAXN * D];   // neighbor means (fp32)
__device__ int    g_cnt[MAXN];
__device__ int    g_rowstart[MAXN];
__device__ int    g_rank[MAXEP];
__device__ int    g_edge[MAXEP];
__device__ int    g_part[NBLK];
__device__ unsigned g_bar_count;
__device__ volatile unsigned g_bar_sense;

typedef unsigned long long u64;

__device__ __forceinline__ u64 pk2(float a, float b) {
    u64 r;
    asm("mov.b64 %0, {%1, %2};" : "=l"(r)
        : "r"(__float_as_uint(a)), "r"(__float_as_uint(b)));
    return r;
}
__device__ __forceinline__ void upk2(u64 v, float& a, float& b) {
    unsigned int x, y;
    asm("mov.b64 {%0, %1}, %2;" : "=r"(x), "=r"(y) : "l"(v));
    a = __uint_as_float(x);
    b = __uint_as_float(y);
}
__device__ __forceinline__ u64 fma2(u64 a, u64 b, u64 c) {
    u64 d;
    asm("fma.rn.f32x2 %0, %1, %2, %3;" : "=l"(d) : "l"(a), "l"(b), "l"(c));
    return d;
}

// Sense-reversing grid barrier (validated in R8/R9).
__device__ __forceinline__ void grid_barrier(unsigned& sense) {
    __syncthreads();
    if (threadIdx.x == 0) {
        sense ^= 1u;
        __threadfence();
        unsigned arrived = atomicAdd(&g_bar_count, 1u) + 1u;
        if (arrived == NBLK) {
            g_bar_count = 0;
            __threadfence();
            g_bar_sense = sense;
        } else {
            while (g_bar_sense != sense) __nanosleep(32);
        }
        __threadfence();
    }
    __syncthreads();
}

// ---------------------------------------------------------------------------
// Gather: warp per node, padded list (sentinel -> zero row n), branch-free.
// Lane loads half2 at column lane*2: 128 B/warp = ONE cache line per row.
// ---------------------------------------------------------------------------
__device__ void gather_phase(const __half* __restrict__ feat, int n) {
    const __half2* __restrict__ base = reinterpret_cast<const __half2*>(feat);
    int nwarps = NBLK * (NTHR / 32);
    int gw = blockIdx.x * (NTHR / 32) + (threadIdx.x >> 5);
    int lane = threadIdx.x & 31;

    for (int node = gw; node < n; node += nwarps) {
        int start = g_rowstart[node];
        int cnt   = g_cnt[node];
        int degp  = (cnt + 7) & ~7;

        float ax = 0.f, ay = 0.f;
        const int* ep = g_edge + start;
        for (int j = 0; j < degp; j += 8) {
            int i0 = __ldg(ep + j + 0);
            int i1 = __ldg(ep + j + 1);
            int i2 = __ldg(ep + j + 2);
            int i3 = __ldg(ep + j + 3);
            int i4 = __ldg(ep + j + 4);
            int i5 = __ldg(ep + j + 5);
            int i6 = __ldg(ep + j + 6);
            int i7 = __ldg(ep + j + 7);
            __half2 v0 = __ldg(base + (size_t)i0 * 32 + lane);
            __half2 v1 = __ldg(base + (size_t)i1 * 32 + lane);
            __half2 v2 = __ldg(base + (size_t)i2 * 32 + lane);
            __half2 v3 = __ldg(base + (size_t)i3 * 32 + lane);
            __half2 v4 = __ldg(base + (size_t)i4 * 32 + lane);
            __half2 v5 = __ldg(base + (size_t)i5 * 32 + lane);
            __half2 v6 = __ldg(base + (size_t)i6 * 32 + lane);
            __half2 v7 = __ldg(base + (size_t)i7 * 32 + lane);
            float2 f0 = __half22float2(v0);
            float2 f1 = __half22float2(v1);
            float2 f2 = __half22float2(v2);
            float2 f3 = __half22float2(v3);
            float2 f4 = __half22float2(v4);
            float2 f5 = __half22float2(v5);
            float2 f6 = __half22float2(v6);
            float2 f7 = __half22float2(v7);
            ax += f0.x + f1.x + f2.x + f3.x + f4.x + f5.x + f6.x + f7.x;
            ay += f0.y + f1.y + f2.y + f3.y + f4.y + f5.y + f6.y + f7.y;
        }
        float inv = 1.0f / fmaxf((float)cnt, 1.0f);
        float2 m; m.x = ax * inv; m.y = ay * inv;
        reinterpret_cast<float2*>(g_mean)[(size_t)node * 32 + lane] = m;
    }
}

// ---------------------------------------------------------------------------
// Combine: out = h@W_self + mean@W_neigh + b [+relu]; f32x2 register tile.
// TO_H116: also store fp16 rows for the next gather.
// ---------------------------------------------------------------------------
template <bool RELU, bool TO_H116>
__device__ void combine_phase(const float* __restrict__ h,
                              const float* __restrict__ Wself,
                              const float* __restrict__ Wneigh,
                              const float* __restrict__ bias,
                              float* __restrict__ out, int n,
                              float* sWs, float* sWn) {
    int tid = threadIdx.x;
    for (int i = tid; i < D * D / 4; i += NTHR) {
        reinterpret_cast<float4*>(sWs)[i] =
            reinterpret_cast<const float4*>(Wself)[i];
        reinterpret_cast<float4*>(sWn)[i] =
            reinterpret_cast<const float4*>(Wneigh)[i];
    }
    __syncthreads();

    int sub = tid & 255;
    int grp = tid >> 8;
    int cg = sub & 15;
    int c0 = cg * 4;
    int ng = sub >> 4;
    int ntiles = (n + 63) / 64;

    u64 b01 = pk2(__ldg(bias + c0 + 0), __ldg(bias + c0 + 1));
    u64 b23 = pk2(__ldg(bias + c0 + 2), __ldg(bias + c0 + 3));

    for (int tile = blockIdx.x * NGROUP + grp; tile < ntiles;
         tile += NBLK * NGROUP) {
        int nbase = tile * 64 + ng * 4;

        bool valid[4];
#pragma unroll
        for (int i = 0; i < 4; i++) valid[i] = (nbase + i) < n;

        u64 acc[4][2];
#pragma unroll
        for (int i = 0; i < 4; i++) { acc[i][0] = b01; acc[i][1] = b23; }

#pragma unroll 4
        for (int k0 = 0; k0 < D; k0 += 4) {
            float4 xv[4], mv[4];
#pragma unroll
            for (int i = 0; i < 4; i++) {
                if (valid[i]) {
                    xv[i] = *reinterpret_cast<const float4*>(
                        h + (size_t)(nbase + i) * D + k0);
                    mv[i] = *reinterpret_cast<const float4*>(
                        g_mean + (size_t)(nbase + i) * D + k0);
                } else {
                    xv[i] = make_float4(0.f, 0.f, 0.f, 0.f);
                    mv[i] = make_float4(0.f, 0.f, 0.f, 0.f);
                }
            }
#pragma unroll
            for (int j = 0; j < 4; j++) {
                int k = k0 + j;
                float4 ws = *reinterpret_cast<const float4*>(sWs + k * D + c0);
                float4 wn = *reinterpret_cast<const float4*>(sWn + k * D + c0);
                u64 ws01 = pk2(ws.x, ws.y), ws23 = pk2(ws.z, ws.w);
                u64 wn01 = pk2(wn.x, wn.y), wn23 = pk2(wn.z, wn.w);
#pragma unroll
                for (int i = 0; i < 4; i++) {
                    float xk = (j == 0) ? xv[i].x : (j == 1) ? xv[i].y
                              : (j == 2) ? xv[i].z : xv[i].w;
                    float mk = (j == 0) ? mv[i].x : (j == 1) ? mv[i].y
                              : (j == 2) ? mv[i].z : mv[i].w;
                    u64 xx = pk2(xk, xk);
                    u64 mm = pk2(mk, mk);
                    acc[i][0] = fma2(xx, ws01, acc[i][0]);
                    acc[i][0] = fma2(mm, wn01, acc[i][0]);
                    acc[i][1] = fma2(xx, ws23, acc[i][1]);
                    acc[i][1] = fma2(mm, wn23, acc[i][1]);
                }
            }
        }

#pragma unroll
        for (int i = 0; i < 4; i++) {
            if (!valid[i]) continue;
            float a0, a1, a2, a3;
            upk2(acc[i][0], a0, a1);
            upk2(acc[i][1], a2, a3);
            if (RELU) {
                a0 = fmaxf(a0, 0.f); a1 = fmaxf(a1, 0.f);
                a2 = fmaxf(a2, 0.f); a3 = fmaxf(a3, 0.f);
            }
            *reinterpret_cast<float4*>(out + (size_t)(nbase + i) * D + c0) =
                make_float4(a0, a1, a2, a3);
            if (TO_H116) {
                __half2* p = reinterpret_cast<__half2*>(
                    g_h116 + (size_t)(nbase + i) * D + c0);
                p[0] = __floats2half2_rn(a0, a1);
                p[1] = __floats2half2_rn(a2, a3);
            }
        }
    }
}

// ---------------------------------------------------------------------------
__global__ void __launch_bounds__(NTHR)
sage_kernel(const float* __restrict__ x,
            const int* __restrict__ src,
            const int* __restrict__ dst,
            const float* __restrict__ W1s, const float* __restrict__ W1n,
            const float* __restrict__ b1,
            const float* __restrict__ W2s, const float* __restrict__ W2n,
            const float* __restrict__ b2,
            float* __restrict__ out, int n, int E) {
    __shared__ float sWs[D * D];
    __shared__ float sWn[D * D];

    unsigned sense = 0;
    const int tid_g = blockIdx.x * NTHR + threadIdx.x;
    const int gstride = NBLK * NTHR;
    const int t = threadIdx.x;

    // ---- phase 0: x -> fp16 table, zero sentinel rows, zero counters ----
    {
        int total4 = n * (D / 4);
        for (int i = tid_g; i < total4; i += gstride) {
            float4 v = reinterpret_cast<const float4*>(x)[i];
            reinterpret_cast<__half2*>(g_x16)[i * 2 + 0] = __floats2half2_rn(v.x, v.y);
            reinterpret_cast<__half2*>(g_x16)[i * 2 + 1] = __floats2half2_rn(v.z, v.w);
        }
        for (int i = tid_g; i < n; i += gstride) g_cnt[i] = 0;
        if (blockIdx.x == 0 && t < D / 2) {
            __half2 z = __floats2half2_rn(0.f, 0.f);
            reinterpret_cast<__half2*>(g_x16 + (size_t)n * D)[t] = z;
            reinterpret_cast<__half2*>(g_h116 + (size_t)n * D)[t] = z;
        }
    }
    grid_barrier(sense);

    // ---- phase 1: histogram + rank capture ----
    for (int e = tid_g; e < E; e += gstride)
        g_rank[e] = atomicAdd(&g_cnt[__ldg(dst + e)], 1);
    grid_barrier(sense);

    // ---- phase 2a: block-local exclusive scan of padded counts ----
    int* s = reinterpret_cast<int*>(sWs);
    const int chunk = (n + NBLK - 1) / NBLK;
    const int node = blockIdx.x * chunk + t;
    int padded = 0;
    if (t < chunk && node < n) padded = (g_cnt[node] + 7) & ~7;
    s[t] = padded;
    __syncthreads();
    for (int off = 1; off < NTHR; off <<= 1) {
        int v = (t >= off) ? s[t - off] : 0;
        __syncthreads();
        s[t] += v;
        __syncthreads();
    }
    int excl = s[t] - padded;
    if (t == NTHR - 1) g_part[blockIdx.x] = s[NTHR - 1];
    grid_barrier(sense);

    // ---- phase 2b: global base + rowstart + sentinel padding edges ----
    {
        int* sp = reinterpret_cast<int*>(sWn);
        if (t < NBLK) sp[t] = g_part[t];
        __syncthreads();
        int base = 0;
        for (int b = 0; b < blockIdx.x; b++) base += sp[b];
        if (t < chunk && node < n) {
            int rs = base + excl;
            g_rowstart[node] = rs;
            int cnt = g_cnt[node];
            int degp = (cnt + 7) & ~7;
            for (int j = cnt; j < degp; j++) g_edge[rs + j] = n;
        }
    }
    grid_barrier(sense);

    // ---- phase 3: fill CSR (atomic-free) ----
    for (int e = tid_g; e < E; e += gstride) {
        int d = __ldg(dst + e);
        g_edge[g_rowstart[d] + g_rank[e]] = __ldg(src + e);
    }
    grid_barrier(sense);

    // ---- phase 4: gather layer 1 (fp16 x rows) ----
    gather_phase(g_x16, n);
    grid_barrier(sense);

    // ---- phase 5: combine layer 1 (relu) -> g_h1 fp32 + g_h116 fp16 ----
    combine_phase<true, true>(x, W1s, W1n, b1, g_h1, n, sWs, sWn);
    grid_barrier(sense);

    // ---- phase 6: gather layer 2 (fp16 h1 rows) ----
    gather_phase(g_h116, n);
    grid_barrier(sense);

    // ---- phase 7: combine layer 2 -> out ----
    combine_phase<false, false>(g_h1, W2s, W2n, b2, out, n, sWs, sWn);
}

// ---------------------------------------------------------------------------
extern "C" void kernel_launch(void* const* d_in, const int* in_sizes, int n_in,
                              void* d_out, int out_size) {
    const float* x        = (const float*)d_in[0];
    const int*   src      = (const int*)d_in[1];
    const int*   dst      = (const int*)d_in[2];
    const float* W1_self  = (const float*)d_in[3];
    const float* W1_neigh = (const float*)d_in[4];
    const float* b1       = (const float*)d_in[5];
    const float* W2_self  = (const float*)d_in[6];
    const float* W2_neigh = (const float*)d_in[7];
    const float* b2       = (const float*)d_in[8];
    float* out = (float*)d_out;

    int n = in_sizes[0] / D;
    int E = in_sizes[1];

    sage_kernel<<<NBLK, NTHR>>>(x, src, dst,
                                W1_self, W1_neigh, b1,
                                W2_self, W2_neigh, b2,
                                out, n, E);
}

// round 11
// speedup vs baseline: 1.5185x; 1.1094x over previous
#include <cuda_runtime.h>
#include <cuda_fp16.h>
#include <cstdint>

// GraphSAGE 2-layer, D=64 — persistent kernel, padded-CSR gather (fp16 rows),
// half-warp-per-node gather with software-pipelined index loads.
//   layer: out = h @ W_self + mean_{in}(h) @ W_neigh + b
//   h1 = relu(layer1(x)); out = layer2(h1)
//
// One launch <<<148, 768>>>, 9 phases / 8 grid barriers (even -> replay-safe):
//   0 x->g_x16 (+zero pad rows), zero cnt | 1 hist(+rank) | 2a scan | 2b base+pad
//   3 fill | 4 gather1 | 5 combine1(relu -> g_h1 + g_h116) | 6 gather2 | 7 combine2

#define D 64
#define MAXN 50048
#define MAXEP 1200000
#define NBLK 148
#define NTHR 768
#define NGROUP (NTHR / 256)

__device__ __half g_x16[MAXN * D];    // fp16 x rows, row n zeroed (sentinel)
__device__ __half g_h116[MAXN * D];   // fp16 h1 rows, row n zeroed
__device__ float  g_h1[MAXN * D];     // fp32 h1 (self path / GEMM)
__device__ float  g_mean[MAXN * D];   // neighbor means (fp32)
__device__ int    g_cnt[MAXN];
__device__ int    g_rowstart[MAXN];
__device__ int    g_rank[MAXEP];
__device__ int    g_edge[MAXEP];
__device__ int    g_part[NBLK];
__device__ unsigned g_bar_count;
__device__ volatile unsigned g_bar_sense;

typedef unsigned long long u64;

__device__ __forceinline__ u64 pk2(float a, float b) {
    u64 r;
    asm("mov.b64 %0, {%1, %2};" : "=l"(r)
        : "r"(__float_as_uint(a)), "r"(__float_as_uint(b)));
    return r;
}
__device__ __forceinline__ void upk2(u64 v, float& a, float& b) {
    unsigned int x, y;
    asm("mov.b64 {%0, %1}, %2;" : "=r"(x), "=r"(y) : "l"(v));
    a = __uint_as_float(x);
    b = __uint_as_float(y);
}
__device__ __forceinline__ u64 fma2(u64 a, u64 b, u64 c) {
    u64 d;
    asm("fma.rn.f32x2 %0, %1, %2, %3;" : "=l"(d) : "l"(a), "l"(b), "l"(c));
    return d;
}

// Sense-reversing grid barrier (validated R8-R10). Even flip count per launch.
__device__ __forceinline__ void grid_barrier(unsigned& sense) {
    __syncthreads();
    if (threadIdx.x == 0) {
        sense ^= 1u;
        __threadfence();
        unsigned arrived = atomicAdd(&g_bar_count, 1u) + 1u;
        if (arrived == NBLK) {
            g_bar_count = 0;
            __threadfence();
            g_bar_sense = sense;
        } else {
            while (g_bar_sense != sense) __nanosleep(32);
        }
        __threadfence();
    }
    __syncthreads();
}

// ---------------------------------------------------------------------------
// Gather v6: HALF-WARP per node (2 nodes concurrently per warp), fp16 rows.
// Lane (0..15 within half-warp) owns 4 columns via one uint2 (= 2x half2).
// Per stripe of 8 padded neighbors:
//   - row loads for stripe j use indices prefetched in stripe j-1
//   - stripe j+1 indices are loaded WHILE stripe j rows are in flight
// Branch-free inner body; sentinel edges -> zero row n.
// ---------------------------------------------------------------------------
__device__ void gather_phase(const __half* __restrict__ feat, int n) {
    const uint2* __restrict__ base = reinterpret_cast<const uint2*>(feat);
    const int nhw = NBLK * (NTHR / 16);               // total half-warps
    const int ghw = blockIdx.x * (NTHR / 16) + (threadIdx.x >> 4);
    const int lane = threadIdx.x & 15;

    for (int node = ghw; node < n; node += nhw) {
        int start = g_rowstart[node];
        int cnt   = g_cnt[node];
        int degp  = (cnt + 7) & ~7;

        float a0 = 0.f, a1 = 0.f, a2 = 0.f, a3 = 0.f;
        const int* ep = g_edge + start;

        if (degp > 0) {
            int idx[8];
#pragma unroll
            for (int u = 0; u < 8; u++) idx[u] = __ldg(ep + u);

            for (int j = 0; j < degp; j += 8) {
                uint2 v[8];
#pragma unroll
                for (int u = 0; u < 8; u++)
                    v[u] = __ldg(base + (size_t)idx[u] * 16 + lane);

                // prefetch next stripe's indices while rows are in flight
                bool more = (j + 8) < degp;
                int nidx[8];
#pragma unroll
                for (int u = 0; u < 8; u++)
                    nidx[u] = more ? __ldg(ep + j + 8 + u) : 0;

#pragma unroll
                for (int u = 0; u < 8; u++) {
                    float2 fa = __half22float2(
                        *reinterpret_cast<__half2*>(&v[u].x));
                    float2 fb = __half22float2(
                        *reinterpret_cast<__half2*>(&v[u].y));
                    a0 += fa.x; a1 += fa.y; a2 += fb.x; a3 += fb.y;
                }
#pragma unroll
                for (int u = 0; u < 8; u++) idx[u] = nidx[u];
            }
        }

        float inv = 1.0f / fmaxf((float)cnt, 1.0f);
        float4 m = make_float4(a0 * inv, a1 * inv, a2 * inv, a3 * inv);
        *reinterpret_cast<float4*>(g_mean + (size_t)node * D + lane * 4) = m;
    }
}

// ---------------------------------------------------------------------------
// Combine: out = h@W_self + mean@W_neigh + b [+relu]; f32x2 register tile.
// TO_H116: also store fp16 rows for the next gather.
// ---------------------------------------------------------------------------
template <bool RELU, bool TO_H116>
__device__ void combine_phase(const float* __restrict__ h,
                              const float* __restrict__ Wself,
                              const float* __restrict__ Wneigh,
                              const float* __restrict__ bias,
                              float* __restrict__ out, int n,
                              float* sWs, float* sWn) {
    int tid = threadIdx.x;
    for (int i = tid; i < D * D / 4; i += NTHR) {
        reinterpret_cast<float4*>(sWs)[i] =
            reinterpret_cast<const float4*>(Wself)[i];
        reinterpret_cast<float4*>(sWn)[i] =
            reinterpret_cast<const float4*>(Wneigh)[i];
    }
    __syncthreads();

    int sub = tid & 255;
    int grp = tid >> 8;
    int cg = sub & 15;
    int c0 = cg * 4;
    int ng = sub >> 4;
    int ntiles = (n + 63) / 64;

    u64 b01 = pk2(__ldg(bias + c0 + 0), __ldg(bias + c0 + 1));
    u64 b23 = pk2(__ldg(bias + c0 + 2), __ldg(bias + c0 + 3));

    for (int tile = blockIdx.x * NGROUP + grp; tile < ntiles;
         tile += NBLK * NGROUP) {
        int nbase = tile * 64 + ng * 4;

        bool valid[4];
#pragma unroll
        for (int i = 0; i < 4; i++) valid[i] = (nbase + i) < n;

        u64 acc[4][2];
#pragma unroll
        for (int i = 0; i < 4; i++) { acc[i][0] = b01; acc[i][1] = b23; }

#pragma unroll 4
        for (int k0 = 0; k0 < D; k0 += 4) {
            float4 xv[4], mv[4];
#pragma unroll
            for (int i = 0; i < 4; i++) {
                if (valid[i]) {
                    xv[i] = *reinterpret_cast<const float4*>(
                        h + (size_t)(nbase + i) * D + k0);
                    mv[i] = *reinterpret_cast<const float4*>(
                        g_mean + (size_t)(nbase + i) * D + k0);
                } else {
                    xv[i] = make_float4(0.f, 0.f, 0.f, 0.f);
                    mv[i] = make_float4(0.f, 0.f, 0.f, 0.f);
                }
            }
#pragma unroll
            for (int j = 0; j < 4; j++) {
                int k = k0 + j;
                float4 ws = *reinterpret_cast<const float4*>(sWs + k * D + c0);
                float4 wn = *reinterpret_cast<const float4*>(sWn + k * D + c0);
                u64 ws01 = pk2(ws.x, ws.y), ws23 = pk2(ws.z, ws.w);
                u64 wn01 = pk2(wn.x, wn.y), wn23 = pk2(wn.z, wn.w);
#pragma unroll
                for (int i = 0; i < 4; i++) {
                    float xk = (j == 0) ? xv[i].x : (j == 1) ? xv[i].y
                              : (j == 2) ? xv[i].z : xv[i].w;
                    float mk = (j == 0) ? mv[i].x : (j == 1) ? mv[i].y
                              : (j == 2) ? mv[i].z : mv[i].w;
                    u64 xx = pk2(xk, xk);
                    u64 mm = pk2(mk, mk);
                    acc[i][0] = fma2(xx, ws01, acc[i][0]);
                    acc[i][0] = fma2(mm, wn01, acc[i][0]);
                    acc[i][1] = fma2(xx, ws23, acc[i][1]);
                    acc[i][1] = fma2(mm, wn23, acc[i][1]);
                }
            }
        }

#pragma unroll
        for (int i = 0; i < 4; i++) {
            if (!valid[i]) continue;
            float a0, a1, a2, a3;
            upk2(acc[i][0], a0, a1);
            upk2(acc[i][1], a2, a3);
            if (RELU) {
                a0 = fmaxf(a0, 0.f); a1 = fmaxf(a1, 0.f);
                a2 = fmaxf(a2, 0.f); a3 = fmaxf(a3, 0.f);
            }
            *reinterpret_cast<float4*>(out + (size_t)(nbase + i) * D + c0) =
                make_float4(a0, a1, a2, a3);
            if (TO_H116) {
                __half2* p = reinterpret_cast<__half2*>(
                    g_h116 + (size_t)(nbase + i) * D + c0);
                p[0] = __floats2half2_rn(a0, a1);
                p[1] = __floats2half2_rn(a2, a3);
            }
        }
    }
}

// ---------------------------------------------------------------------------
__global__ void __launch_bounds__(NTHR)
sage_kernel(const float* __restrict__ x,
            const int* __restrict__ src,
            const int* __restrict__ dst,
            const float* __restrict__ W1s, const float* __restrict__ W1n,
            const float* __restrict__ b1,
            const float* __restrict__ W2s, const float* __restrict__ W2n,
            const float* __restrict__ b2,
            float* __restrict__ out, int n, int E) {
    __shared__ float sWs[D * D];
    __shared__ float sWn[D * D];

    unsigned sense = 0;
    const int tid_g = blockIdx.x * NTHR + threadIdx.x;
    const int gstride = NBLK * NTHR;
    const int t = threadIdx.x;

    // ---- phase 0: x -> fp16 table, zero sentinel rows, zero counters ----
    {
        int total4 = n * (D / 4);
        for (int i = tid_g; i < total4; i += gstride) {
            float4 v = reinterpret_cast<const float4*>(x)[i];
            reinterpret_cast<__half2*>(g_x16)[i * 2 + 0] = __floats2half2_rn(v.x, v.y);
            reinterpret_cast<__half2*>(g_x16)[i * 2 + 1] = __floats2half2_rn(v.z, v.w);
        }
        for (int i = tid_g; i < n; i += gstride) g_cnt[i] = 0;
        if (blockIdx.x == 0 && t < D / 2) {
            __half2 z = __floats2half2_rn(0.f, 0.f);
            reinterpret_cast<__half2*>(g_x16 + (size_t)n * D)[t] = z;
            reinterpret_cast<__half2*>(g_h116 + (size_t)n * D)[t] = z;
        }
    }
    grid_barrier(sense);

    // ---- phase 1: histogram + rank capture ----
    for (int e = tid_g; e < E; e += gstride)
        g_rank[e] = atomicAdd(&g_cnt[__ldg(dst + e)], 1);
    grid_barrier(sense);

    // ---- phase 2a: block-local exclusive scan of padded counts ----
    int* s = reinterpret_cast<int*>(sWs);
    const int chunk = (n + NBLK - 1) / NBLK;
    const int node = blockIdx.x * chunk + t;
    int padded = 0;
    if (t < chunk && node < n) padded = (g_cnt[node] + 7) & ~7;
    s[t] = padded;
    __syncthreads();
    for (int off = 1; off < NTHR; off <<= 1) {
        int v = (t >= off) ? s[t - off] : 0;
        __syncthreads();
        s[t] += v;
        __syncthreads();
    }
    int excl = s[t] - padded;
    if (t == NTHR - 1) g_part[blockIdx.x] = s[NTHR - 1];
    grid_barrier(sense);

    // ---- phase 2b: global base + rowstart + sentinel padding edges ----
    {
        int* sp = reinterpret_cast<int*>(sWn);
        if (t < NBLK) sp[t] = g_part[t];
        __syncthreads();
        int base = 0;
        for (int b = 0; b < blockIdx.x; b++) base += sp[b];
        if (t < chunk && node < n) {
            int rs = base + excl;
            g_rowstart[node] = rs;
            int cnt = g_cnt[node];
            int degp = (cnt + 7) & ~7;
            for (int j = cnt; j < degp; j++) g_edge[rs + j] = n;
        }
    }
    grid_barrier(sense);

    // ---- phase 3: fill CSR (atomic-free) ----
    for (int e = tid_g; e < E; e += gstride) {
        int d = __ldg(dst + e);
        g_edge[g_rowstart[d] + g_rank[e]] = __ldg(src + e);
    }
    grid_barrier(sense);

    // ---- phase 4: gather layer 1 (fp16 x rows) ----
    gather_phase(g_x16, n);
    grid_barrier(sense);

    // ---- phase 5: combine layer 1 (relu) -> g_h1 fp32 + g_h116 fp16 ----
    combine_phase<true, true>(x, W1s, W1n, b1, g_h1, n, sWs, sWn);
    grid_barrier(sense);

    // ---- phase 6: gather layer 2 (fp16 h1 rows) ----
    gather_phase(g_h116, n);
    grid_barrier(sense);

    // ---- phase 7: combine layer 2 -> out ----
    combine_phase<false, false>(g_h1, W2s, W2n, b2, out, n, sWs, sWn);
}

// ---------------------------------------------------------------------------
extern "C" void kernel_launch(void* const* d_in, const int* in_sizes, int n_in,
                              void* d_out, int out_size) {
    const float* x        = (const float*)d_in[0];
    const int*   src      = (const int*)d_in[1];
    const int*   dst      = (const int*)d_in[2];
    const float* W1_self  = (const float*)d_in[3];
    const float* W1_neigh = (const float*)d_in[4];
    const float* b1       = (const float*)d_in[5];
    const float* W2_self  = (const float*)d_in[6];
    const float* W2_neigh = (const float*)d_in[7];
    const float* b2       = (const float*)d_in[8];
    float* out = (float*)d_out;

    int n = in_sizes[0] / D;
    int E = in_sizes[1];

    sage_kernel<<<NBLK, NTHR>>>(x, src, dst,
                                W1_self, W1_neigh, b1,
                                W2_self, W2_neigh, b2,
                                out, n, E);
}